// round 15
// baseline (speedup 1.0000x reference)
#include <cuda_runtime.h>
#include <math.h>

#define Bn 2
#define Ln 2048
#define Dn 512
#define Nn 4096
#define Gn 64
#define Tn 512
#define EPSN 1e-12f
#define EPSW 1e-8f
#define CT 512
#define CE 4
#define RND 3
#define ROWSA (Ln + RND * (Ln / 2))

// ---------------- scratch ----------------
__device__ __align__(256) float g_gn[Bn * ROWSA * Gn];
__device__ float g_norms[Bn * Ln];
__device__ float g_sim[Bn * Ln];
__device__ float g_coef[Bn * Ln];
__device__ unsigned short g_slo[Bn][Ln + 1];
__device__ int   g_srow[Bn][Ln];

// per-slot endpoint descriptors
__device__ int   g_iA[Bn][Ln];
__device__ int   g_iB[Bn][Ln];
__device__ float g_fw1[Bn][Ln];
__device__ float g_fw2[Bn][Ln];
__device__ int   g_isp[Bn][Ln];

// final-round per-slot coef factors (consumed by k_apply chunk 0)
__device__ float g_lfa[Bn][Tn];
__device__ float g_lfb[Bn][Tn];
__device__ int   g_ltb[Bn][Tn];

struct PairRec { int p, ta, tb, tc; float wi, wj; int rowA, rowB, destRow; };
__device__ PairRec g_pairs[Bn][1024];
__device__ int g_edges[Bn][2048];
__device__ int g_pc[Bn], g_ec[Bn], g_nn[Bn], g_rm[Bn];

// ---------------- K1: g = x @ w^T, norms, gn — smem-tiled GEMM + init ---------
__global__ __launch_bounds__(256) void k_gn(const float* __restrict__ x,
                                            const float* __restrict__ w)
{
    const int tid = threadIdx.x;
    const int tok0 = blockIdx.x * 32;
    const int gt = tid & 15;
    const int tt = tid >> 4;
    const int bb = tok0 / Ln;
    const int t0 = tok0 - bb * Ln;

    if (tid < 32) {
        int t = t0 + tid;
        g_coef[bb * Ln + t] = 1.0f;
        g_slo[bb][t] = (unsigned short)t;
        g_srow[bb][t] = t;
        if (t == 0) {
            g_slo[bb][Ln] = (unsigned short)Ln;
            g_nn[bb] = Ln;
            g_rm[bb] = Ln - Tn;
            g_pc[bb] = 0;
            g_ec[bb] = 0;
        }
    }

    __shared__ float xs[32][68];
    __shared__ float wsT[64][68];
    __shared__ float psum[4][32];
    __shared__ float snorm[32];

    float acc0x = 0.f, acc0y = 0.f, acc0z = 0.f, acc0w = 0.f;
    float acc1x = 0.f, acc1y = 0.f, acc1z = 0.f, acc1w = 0.f;

    const int xrow = tid >> 3;
    const int xf4  = tid & 7;
    const int wrow = tid >> 2;
    const int wf4  = tid & 3;

    for (int kt = 0; kt < 8; kt++) {
        {
            const float4* xg = (const float4*)(x + (size_t)(tok0 + xrow) * Dn + kt * 64);
            float4* xsr = (float4*)&xs[xrow][0];
#pragma unroll
            for (int q = 0; q < 2; q++) xsr[xf4 + q * 8] = xg[xf4 + q * 8];
        }
        {
            const float4* wg = (const float4*)(w + (size_t)wrow * Dn + kt * 64);
#pragma unroll
            for (int q = 0; q < 4; q++) {
                float4 v = wg[wf4 + q * 4];
                int kb = (wf4 + q * 4) * 4;
                wsT[kb + 0][wrow] = v.x;
                wsT[kb + 1][wrow] = v.y;
                wsT[kb + 2][wrow] = v.z;
                wsT[kb + 3][wrow] = v.w;
            }
        }
        __syncthreads();

#pragma unroll
        for (int k4 = 0; k4 < 16; k4++) {
            float4 xv0 = *(const float4*)&xs[tt][k4 * 4];
            float4 xv1 = *(const float4*)&xs[tt + 16][k4 * 4];
#pragma unroll
            for (int e = 0; e < 4; e++) {
                float4 wv = *(const float4*)&wsT[k4 * 4 + e][gt * 4];
                float x0 = (e == 0) ? xv0.x : (e == 1) ? xv0.y : (e == 2) ? xv0.z : xv0.w;
                float x1 = (e == 0) ? xv1.x : (e == 1) ? xv1.y : (e == 2) ? xv1.z : xv1.w;
                acc0x += x0 * wv.x; acc0y += x0 * wv.y; acc0z += x0 * wv.z; acc0w += x0 * wv.w;
                acc1x += x1 * wv.x; acc1y += x1 * wv.y; acc1z += x1 * wv.z; acc1w += x1 * wv.w;
            }
        }
        __syncthreads();
    }

    xs[tt][gt * 4 + 0] = acc0x;  xs[tt][gt * 4 + 1] = acc0y;
    xs[tt][gt * 4 + 2] = acc0z;  xs[tt][gt * 4 + 3] = acc0w;
    xs[tt + 16][gt * 4 + 0] = acc1x;  xs[tt + 16][gt * 4 + 1] = acc1y;
    xs[tt + 16][gt * 4 + 2] = acc1z;  xs[tt + 16][gt * 4 + 3] = acc1w;
    __syncthreads();

    if (tid < 128) {
        int tok = tid & 31, p = tid >> 5;
        float s = 0.f;
#pragma unroll
        for (int gi = p * 16; gi < p * 16 + 16; gi++) { float v = xs[tok][gi]; s += v * v; }
        psum[p][tok] = s;
    }
    __syncthreads();
    if (tid < 32) {
        float ss = ((psum[0][tid] + psum[1][tid]) + psum[2][tid]) + psum[3][tid];
        float nm = sqrtf(ss);
        snorm[tid] = fmaxf(nm, EPSN);
        g_norms[tok0 + tid] = nm;
    }
    __syncthreads();

    {
        int row = tid >> 3;
        float inv = 1.f / snorm[row];
        float4* dst = (float4*)(g_gn + ((size_t)bb * ROWSA + t0 + row) * Gn);
#pragma unroll
        for (int q = 0; q < 2; q++) {
            int f4 = (tid & 7) + q * 8;
            float4 v = *(const float4*)&xs[row][f4 * 4];
            v.x *= inv; v.y *= inv; v.z *= inv; v.w *= inv;
            dst[f4] = v;
        }
    }
}

// ---------------- K1b: round-1 adjacent sims ----------------
__global__ void k_sim()
{
    int b = blockIdx.y;
    int warp = threadIdx.x >> 5;
    int lane = threadIdx.x & 31;
    int i = (blockIdx.x * 8 + warp) * 2 + (lane >> 4);
    int l = lane & 15;
    float d = 0.f;
    if (i < Ln - 1) {
        const float4* A = (const float4*)(g_gn + ((size_t)b * ROWSA + i) * Gn);
        float4 a = A[l], c = A[l + 16];
        d = a.x * c.x + a.y * c.y + a.z * c.z + a.w * c.w;
    }
    d += __shfl_down_sync(0xffffffffu, d, 8, 16);
    d += __shfl_down_sync(0xffffffffu, d, 4, 16);
    d += __shfl_down_sync(0xffffffffu, d, 2, 16);
    d += __shfl_down_sync(0xffffffffu, d, 1, 16);
    if (l == 0 && i < Ln - 1) g_sim[b * Ln + i] = d;
}

// ---------------- K2a: per-round control (scalar only; CT=512) ----------------
__global__ __launch_bounds__(CT) void k_ctl(int rnd, int fin)
{
    const int b = blockIdx.x;
    const int tid = threadIdx.x;
    const int wid = tid >> 5;
    const int lane = tid & 31;

    int n = g_nn[b], rem = g_rm[b];
    if (rem <= 0 || n < 2) {
        if (tid == 0) { g_pc[b] = 0; g_ec[b] = 0; }
        return;
    }
    int r_step = min(rem, n >> 1);

    __shared__ float s_sim[Ln];
    __shared__ float s_norm[Ln];
    __shared__ unsigned short s_lo[Ln + 1];
    __shared__ int s_row[Ln];
    __shared__ unsigned char s_flag[Ln];
    __shared__ unsigned char s_isPair[Ln];
    __shared__ unsigned long long s_key[Ln];
    __shared__ int s_part[CT / 32];
    __shared__ int sh_pc, sh_ec;

    for (int i = tid; i < n; i += CT) {
        s_sim[i]  = g_sim[b * Ln + i];
        s_norm[i] = g_norms[b * Ln + i];
        s_lo[i]   = g_slo[b][i];
        s_row[i]  = g_srow[b][i];
    }
    if (tid == 0) { s_lo[n] = (unsigned short)Ln; sh_pc = 0; sh_ec = 0; }
    __syncthreads();

    int base = tid * CE;
    unsigned pre = 0, parF = 0, parB = 0;

    int run = -1;
#pragma unroll
    for (int e = 0; e < CE; e++) {
        int i = base + e;
        if (i < n - 1) {
            bool bnd = (i == 0) || (s_sim[i - 1] < s_sim[i]);
            if (bnd) run = i;
            if (run < 0) pre |= (1u << e);
            else if (((i - run) & 1) == 0) parF |= (1u << e);
        }
    }
    int incl = run;
#pragma unroll
    for (int off = 1; off < 32; off <<= 1) {
        int v = __shfl_up_sync(0xffffffffu, incl, off);
        if (lane >= off) incl = max(incl, v);
    }
    int excl = __shfl_up_sync(0xffffffffu, incl, 1);
    if (lane == 0) excl = -1;
    if (lane == 31) s_part[wid] = incl;
    __syncthreads();
    {
        int carry = excl;
        for (int w2 = 0; w2 < wid; w2++) carry = max(carry, s_part[w2]);
        if (pre) {
#pragma unroll
            for (int e = 0; e < CE; e++)
                if ((pre >> e) & 1u) {
                    if ((((base + e) - carry) & 1) == 0) parF |= (1u << e);
                }
        }
    }
    __syncthreads();

    pre = 0; run = 0x7fffffff;
#pragma unroll
    for (int e = CE - 1; e >= 0; e--) {
        int i = base + e;
        if (i < n - 1) {
            bool bnd = (i == n - 2) || (s_sim[i + 1] <= s_sim[i]);
            if (bnd) run = i;
            if (run == 0x7fffffff) pre |= (1u << e);
            else if (((run - i) & 1) == 0) parB |= (1u << e);
        }
    }
    int sincl = run;
#pragma unroll
    for (int off = 1; off < 32; off <<= 1) {
        int v = __shfl_down_sync(0xffffffffu, sincl, off);
        if (lane + off < 32) sincl = min(sincl, v);
    }
    int sexcl = __shfl_down_sync(0xffffffffu, sincl, 1);
    if (lane == 31) sexcl = 0x7fffffff;
    if (lane == 0) s_part[wid] = sincl;
    __syncthreads();
    {
        int carry = sexcl;
        for (int w2 = wid + 1; w2 < CT / 32; w2++) carry = min(carry, s_part[w2]);
        if (pre) {
#pragma unroll
            for (int e = 0; e < CE; e++)
                if ((pre >> e) & 1u) {
                    if (((carry - (base + e)) & 1) == 0) parB |= (1u << e);
                }
        }
    }

    unsigned tk = parF & parB;
    int lm = 0;
#pragma unroll
    for (int e = 0; e < CE; e++) {
        int i = base + e;
        if (i < n - 1) {
            unsigned t1 = (tk >> e) & 1u;
            s_flag[i] = (unsigned char)t1;
            lm += (int)t1;
        }
    }
#pragma unroll
    for (int off = 16; off > 0; off >>= 1) lm += __shfl_down_sync(0xffffffffu, lm, off);
    __syncthreads();
    if (lane == 0) s_part[wid] = lm;
    __syncthreads();
    int m = 0;
    for (int w2 = 0; w2 < CT / 32; w2++) m += s_part[w2];
    int cnt = min(m, r_step);

    if (m > r_step) {
        int P = 1; while (P < n - 1) P <<= 1;
        for (int i = tid; i < P; i += CT) {
            unsigned long long key = 0ull;
            if (i < n - 1 && (s_flag[i] & 1)) {
                unsigned u = __float_as_uint(s_sim[i]);
                unsigned sk = (u & 0x80000000u) ? ~u : (u | 0x80000000u);
                key = ((unsigned long long)sk << 16) | (unsigned)(Ln - 1 - i);
            }
            s_key[i] = key;
        }
        __syncthreads();
        for (int kk = 2; kk <= P; kk <<= 1) {
            for (int j = kk >> 1; j > 0; j >>= 1) {
                for (int i = tid; i < P; i += CT) {
                    int ixj = i ^ j;
                    if (ixj > i) {
                        unsigned long long a = s_key[i], c = s_key[ixj];
                        bool dir = ((i & kk) == 0);
                        if (dir ? (a < c) : (a > c)) { s_key[i] = c; s_key[ixj] = a; }
                    }
                }
                __syncthreads();
            }
        }
        for (int r = tid; r < r_step; r += CT) {
            int idx = Ln - 1 - (int)(s_key[r] & 0xFFFFull);
            s_flag[idx] |= 2;
        }
    } else {
        for (int i = tid; i < n - 1; i += CT)
            if (s_flag[i] & 1) s_flag[i] |= 2;
    }
    __syncthreads();

    int keepMask = 0, loc = 0;
#pragma unroll
    for (int e = 0; e < CE; e++) {
        int i = base + e;
        bool kp = (i < n) && !(i > 0 && (s_flag[i - 1] & 2));
        if (kp) { keepMask |= (1 << e); loc++; }
    }
    int inc = loc;
#pragma unroll
    for (int off = 1; off < 32; off <<= 1) {
        int v = __shfl_up_sync(0xffffffffu, inc, off);
        if (lane >= off) inc += v;
    }
    int exc = inc - loc;
    if (lane == 31) s_part[wid] = inc;
    __syncthreads();
    int carry = 0;
    for (int w2 = 0; w2 < wid; w2++) carry += s_part[w2];
    int p = carry + exc;
#pragma unroll
    for (int e = 0; e < CE; e++) {
        if ((keepMask >> e) & 1) {
            int i = base + e;
            bool isSel = (i < n - 1) && (s_flag[i] & 2);
            float wi2 = s_norm[i];
            g_norms[b * Ln + p] = isSel ? (wi2 + s_norm[i + 1]) * 0.5f : wi2;
            g_sim[b * Ln + p]   = s_sim[i];
            g_slo[b][p]         = s_lo[i];
            s_isPair[p] = isSel ? 1 : 0;
            g_iA[b][p]  = s_row[i];
            g_iB[b][p]  = isSel ? s_row[i + 1] : s_row[i];
            g_fw1[b][p] = wi2;
            g_fw2[b][p] = isSel ? s_norm[i + 1] : 0.f;
            g_isp[b][p] = isSel ? 1 : 0;
            if (fin && p < Tn) {
                // final-round coef factors, applied in k_apply chunk 0.
                if (isSel) {
                    float tot = wi2 + s_norm[i + 1] + EPSW;  // same order as pair path
                    g_lfa[b][p] = wi2 / tot;
                    g_lfb[b][p] = s_norm[i + 1] / tot;
                    g_ltb[b][p] = s_lo[i + 1];
                } else {
                    g_lfa[b][p] = 1.f;
                    g_lfb[b][p] = 1.f;
                    g_ltb[b][p] = 0;
                }
            }
            if (isSel) {
                int k = atomicAdd(&sh_pc, 1);
                int destRow = Ln + rnd * (Ln / 2) + k;
                g_srow[b][p] = destRow;
                PairRec pr;
                pr.p = p; pr.ta = s_lo[i]; pr.tb = s_lo[i + 1]; pr.tc = s_lo[i + 2];
                pr.wi = wi2; pr.wj = s_norm[i + 1];
                pr.rowA = s_row[i]; pr.rowB = s_row[i + 1]; pr.destRow = destRow;
                g_pairs[b][k] = pr;
            } else {
                g_srow[b][p] = s_row[i];
            }
            p++;
        }
    }
    __syncthreads();

    int n_new = n - cnt;
    int pc = sh_pc;
    if (!fin) {
        for (int k = tid; k < pc; k += CT) {
            int pp = g_pairs[b][k].p;
            if (pp + 1 < n_new) g_edges[b][atomicAdd(&sh_ec, 1)] = pp;
            if (pp > 0 && !s_isPair[pp - 1]) g_edges[b][atomicAdd(&sh_ec, 1)] = pp - 1;
        }
        __syncthreads();
    }

    if (tid == 0) {
        g_slo[b][n_new] = (unsigned short)Ln;
        g_nn[b] = n_new;
        g_rm[b] = rem - cnt;
        g_pc[b] = pc;
        g_ec[b] = sh_ec;
    }
}

// slot endpoint value from OLD rows (bit-matching the merge path)
__device__ __forceinline__ float4 slot_value(int b, int pos, int l, bool valid)
{
    int rowA = 0, rowB = 0, isp = 0;
    float w1 = 1.f, w2 = 0.f;
    if (valid) {
        rowA = g_iA[b][pos]; rowB = g_iB[b][pos];
        w1 = g_fw1[b][pos];  w2 = g_fw2[b][pos];
        isp = g_isp[b][pos];
    }
    float4 a = ((const float4*)(g_gn + ((size_t)b * ROWSA + rowA) * Gn))[l];
    float4 c = ((const float4*)(g_gn + ((size_t)b * ROWSA + rowB) * Gn))[l];
    float tot = w1 + w2 + EPSW;
    float mx = (w1 * a.x + w2 * c.x) / tot;
    float my = (w1 * a.y + w2 * c.y) / tot;
    float mz = (w1 * a.z + w2 * c.z) / tot;
    float mw = (w1 * a.w + w2 * c.w) / tot;
    float ssq = mx * mx + my * my + mz * mz + mw * mw;
    ssq += __shfl_xor_sync(0xffffffffu, ssq, 8, 16);
    ssq += __shfl_xor_sync(0xffffffffu, ssq, 4, 16);
    ssq += __shfl_xor_sync(0xffffffffu, ssq, 2, 16);
    ssq += __shfl_xor_sync(0xffffffffu, ssq, 1, 16);
    float inv = 1.f / fmaxf(sqrtf(ssq), EPSN);
    float4 v;
    v.x = isp ? mx * inv : a.x;
    v.y = isp ? my * inv : a.y;
    v.z = isp ? mz * inv : a.z;
    v.w = isp ? mw * inv : a.w;
    return v;
}

// ---------------- K2b: fused pair merges + edge sims ----------------
__global__ __launch_bounds__(256) void k_pair()
{
    int b = blockIdx.y;
    int l = threadIdx.x & 15;

    if (blockIdx.x < 64) {
        int hw = blockIdx.x * 16 + (threadIdx.x >> 4);
        int cnt = g_pc[b];
        bool valid = hw < cnt;

        int ta = 0, tb = 0, tc = 0, rowA = 0, rowB = 0, destRow = 0;
        float wi = 0.f, wj = 0.f, tot = 1.f;
        float4 a = make_float4(0.f, 0.f, 0.f, 0.f);
        float4 c = a;
        if (valid) {
            PairRec pr = g_pairs[b][hw];
            ta = pr.ta; tb = pr.tb; tc = pr.tc; wi = pr.wi; wj = pr.wj;
            rowA = pr.rowA; rowB = pr.rowB; destRow = pr.destRow;
            tot = wi + wj + EPSW;
            a = ((const float4*)(g_gn + ((size_t)b * ROWSA + rowA) * Gn))[l];
            c = ((const float4*)(g_gn + ((size_t)b * ROWSA + rowB) * Gn))[l];
        }
        float mx = (wi * a.x + wj * c.x) / tot;
        float my = (wi * a.y + wj * c.y) / tot;
        float mz = (wi * a.z + wj * c.z) / tot;
        float mw = (wi * a.w + wj * c.w) / tot;
        float ssq = mx * mx + my * my + mz * mz + mw * mw;
        ssq += __shfl_xor_sync(0xffffffffu, ssq, 8, 16);
        ssq += __shfl_xor_sync(0xffffffffu, ssq, 4, 16);
        ssq += __shfl_xor_sync(0xffffffffu, ssq, 2, 16);
        ssq += __shfl_xor_sync(0xffffffffu, ssq, 1, 16);
        if (valid) {
            float inv = 1.f / fmaxf(sqrtf(ssq), EPSN);
            float4 o; o.x = mx * inv; o.y = my * inv; o.z = mz * inv; o.w = mw * inv;
            ((float4*)(g_gn + ((size_t)b * ROWSA + destRow) * Gn))[l] = o;
            float fa = wi / tot, fb = wj / tot;
            float* cb = g_coef + b * Ln;
            for (int t = ta + l; t < tb; t += 16) cb[t] *= fa;
            for (int t = tb + l; t < tc; t += 16) cb[t] *= fb;
        }
    } else {
        int hw = (blockIdx.x - 64) * 16 + (threadIdx.x >> 4);
        int ec = g_ec[b];
        bool valid = hw < ec;
        int pos = valid ? g_edges[b][hw] : 0;

        float4 vu = slot_value(b, pos, l, valid);
        float4 vv = slot_value(b, pos + 1, l, valid);
        float d = vu.x * vv.x + vu.y * vv.y + vu.z * vv.z + vu.w * vv.w;
        d += __shfl_down_sync(0xffffffffu, d, 8, 16);
        d += __shfl_down_sync(0xffffffffu, d, 4, 16);
        d += __shfl_down_sync(0xffffffffu, d, 2, 16);
        d += __shfl_down_sync(0xffffffffu, d, 1, 16);
        if (valid && l == 0) g_sim[b * Ln + pos] = d;
    }
}

// ---------------- K3: apply plan — 256 threads, token-parity split ------------
__global__ __launch_bounds__(256) void k_apply(const float* __restrict__ x,
                                               const float* __restrict__ s,
                                               float* __restrict__ out)
{
    int kslot = blockIdx.x;
    int chunk = blockIdx.y;
    int b = blockIdx.z;
    int lo = g_slo[b][kslot];
    int hi = g_slo[b][kslot + 1];
    int t4 = threadIdx.x & 127;
    int half = threadIdx.x >> 7;

    __shared__ float4 sbuf[128];
    float4 acc = make_float4(0.f, 0.f, 0.f, 0.f);

    if (chunk == 0) {
        float lfa = g_lfa[b][kslot], lfb = g_lfb[b][kslot];
        int ltb = g_ltb[b][kslot];
#pragma unroll 2
        for (int t = lo + half; t < hi; t += 2) {
            float f = (t < ltb) ? lfa : lfb;
            float c = g_coef[b * Ln + t] * f;
            float4 v = ((const float4*)(x + ((size_t)b * Ln + t) * Dn))[t4];
            acc.x += c * v.x; acc.y += c * v.y; acc.z += c * v.z; acc.w += c * v.w;
        }
    } else {
        int c0 = (chunk - 1) * 512;
#pragma unroll 2
        for (int t = lo + half; t < hi; t += 2) {
            float4 v = ((const float4*)(s + ((size_t)b * Ln + t) * Nn + c0))[t4];
            acc.x += v.x; acc.y += v.y; acc.z += v.z; acc.w += v.w;
        }
    }

    if (half) sbuf[t4] = acc;
    __syncthreads();
    if (!half) {
        float4 o = sbuf[t4];
        acc.x += o.x; acc.y += o.y; acc.z += o.z; acc.w += o.w;
        if (chunk == 0) {
            ((float4*)(out + ((size_t)b * Tn + kslot) * Dn))[t4] = acc;
        } else {
            int c0 = (chunk - 1) * 512;
            ((float4*)(out + (size_t)Bn * Tn * Dn + ((size_t)b * Tn + kslot) * Nn + c0))[t4] = acc;
        }
    }
}

// ---------------- launch ----------------
extern "C" void kernel_launch(void* const* d_in, const int* in_sizes, int n_in,
                              void* d_out, int out_size)
{
    const float* x = (const float*)d_in[0];
    const float* src = (const float*)d_in[1];
    const float* w = (const float*)d_in[2];
    float* out = (float*)d_out;

    k_gn<<<Bn * Ln / 32, 256>>>(x, w);            // #0
    k_sim<<<dim3(128, Bn), 256>>>();              // #1
    for (int r = 0; r < RND; r++) {
        int fin = (r == RND - 1);
        k_ctl<<<Bn, CT>>>(r, fin);                // #2,4,6
        if (!fin) k_pair<<<dim3(192, Bn), 256>>>();  // #3,5
    }
    dim3 g3(Tn, 1 + Nn / 512, Bn);
    k_apply<<<g3, 256>>>(x, src, out);            // #7 — 8 launches total
}

// round 16
// speedup vs baseline: 1.0304x; 1.0304x over previous
#include <cuda_runtime.h>
#include <math.h>

#define Bn 2
#define Ln 2048
#define Dn 512
#define Nn 4096
#define Gn 64
#define Tn 512
#define EPSN 1e-12f
#define EPSW 1e-8f
#define CT 512
#define CE 4
#define RND 3
#define ROWSA (Ln + RND * (Ln / 2))

// ---------------- scratch ----------------
__device__ __align__(256) float g_gn[Bn * ROWSA * Gn];
__device__ float g_norms[Bn * Ln];
__device__ float g_sim[Bn * Ln];
__device__ float g_coef[Bn * Ln];
__device__ unsigned short g_slo[Bn][Ln + 1];
__device__ int   g_srow[Bn][Ln];

// per-slot endpoint descriptors
__device__ int   g_iA[Bn][Ln];
__device__ int   g_iB[Bn][Ln];
__device__ float g_fw1[Bn][Ln];
__device__ float g_fw2[Bn][Ln];
__device__ int   g_isp[Bn][Ln];

// final-round per-slot coef factors (consumed by k_apply chunk 0)
__device__ float g_lfa[Bn][Tn];
__device__ float g_lfb[Bn][Tn];
__device__ int   g_ltb[Bn][Tn];

struct PairRec { int p, ta, tb, tc; float wi, wj; int rowA, rowB, destRow; };
__device__ PairRec g_pairs[Bn][1024];
__device__ int g_edges[Bn][2048];
__device__ int g_pc[Bn], g_ec[Bn], g_nn[Bn], g_rm[Bn];

// ---------------- K1: g = x @ w^T, norms, gn — smem-tiled GEMM + init ---------
__global__ __launch_bounds__(256) void k_gn(const float* __restrict__ x,
                                            const float* __restrict__ w)
{
    const int tid = threadIdx.x;
    const int tok0 = blockIdx.x * 32;
    const int gt = tid & 15;
    const int tt = tid >> 4;
    const int bb = tok0 / Ln;
    const int t0 = tok0 - bb * Ln;

    if (tid < 32) {
        int t = t0 + tid;
        g_coef[bb * Ln + t] = 1.0f;
        g_slo[bb][t] = (unsigned short)t;
        g_srow[bb][t] = t;
        if (t == 0) {
            g_slo[bb][Ln] = (unsigned short)Ln;
            g_nn[bb] = Ln;
            g_rm[bb] = Ln - Tn;
            g_pc[bb] = 0;
            g_ec[bb] = 0;
        }
    }

    __shared__ float xs[32][68];
    __shared__ float wsT[64][68];
    __shared__ float psum[4][32];
    __shared__ float snorm[32];

    float acc0x = 0.f, acc0y = 0.f, acc0z = 0.f, acc0w = 0.f;
    float acc1x = 0.f, acc1y = 0.f, acc1z = 0.f, acc1w = 0.f;

    const int xrow = tid >> 3;
    const int xf4  = tid & 7;
    const int wrow = tid >> 2;
    const int wf4  = tid & 3;

    for (int kt = 0; kt < 8; kt++) {
        {
            const float4* xg = (const float4*)(x + (size_t)(tok0 + xrow) * Dn + kt * 64);
            float4* xsr = (float4*)&xs[xrow][0];
#pragma unroll
            for (int q = 0; q < 2; q++) xsr[xf4 + q * 8] = xg[xf4 + q * 8];
        }
        {
            const float4* wg = (const float4*)(w + (size_t)wrow * Dn + kt * 64);
#pragma unroll
            for (int q = 0; q < 4; q++) {
                float4 v = wg[wf4 + q * 4];
                int kb = (wf4 + q * 4) * 4;
                wsT[kb + 0][wrow] = v.x;
                wsT[kb + 1][wrow] = v.y;
                wsT[kb + 2][wrow] = v.z;
                wsT[kb + 3][wrow] = v.w;
            }
        }
        __syncthreads();

#pragma unroll
        for (int k4 = 0; k4 < 16; k4++) {
            float4 xv0 = *(const float4*)&xs[tt][k4 * 4];
            float4 xv1 = *(const float4*)&xs[tt + 16][k4 * 4];
#pragma unroll
            for (int e = 0; e < 4; e++) {
                float4 wv = *(const float4*)&wsT[k4 * 4 + e][gt * 4];
                float x0 = (e == 0) ? xv0.x : (e == 1) ? xv0.y : (e == 2) ? xv0.z : xv0.w;
                float x1 = (e == 0) ? xv1.x : (e == 1) ? xv1.y : (e == 2) ? xv1.z : xv1.w;
                acc0x += x0 * wv.x; acc0y += x0 * wv.y; acc0z += x0 * wv.z; acc0w += x0 * wv.w;
                acc1x += x1 * wv.x; acc1y += x1 * wv.y; acc1z += x1 * wv.z; acc1w += x1 * wv.w;
            }
        }
        __syncthreads();
    }

    xs[tt][gt * 4 + 0] = acc0x;  xs[tt][gt * 4 + 1] = acc0y;
    xs[tt][gt * 4 + 2] = acc0z;  xs[tt][gt * 4 + 3] = acc0w;
    xs[tt + 16][gt * 4 + 0] = acc1x;  xs[tt + 16][gt * 4 + 1] = acc1y;
    xs[tt + 16][gt * 4 + 2] = acc1z;  xs[tt + 16][gt * 4 + 3] = acc1w;
    __syncthreads();

    if (tid < 128) {
        int tok = tid & 31, p = tid >> 5;
        float s = 0.f;
#pragma unroll
        for (int gi = p * 16; gi < p * 16 + 16; gi++) { float v = xs[tok][gi]; s += v * v; }
        psum[p][tok] = s;
    }
    __syncthreads();
    if (tid < 32) {
        float ss = ((psum[0][tid] + psum[1][tid]) + psum[2][tid]) + psum[3][tid];
        float nm = sqrtf(ss);
        snorm[tid] = fmaxf(nm, EPSN);
        g_norms[tok0 + tid] = nm;
    }
    __syncthreads();

    {
        int row = tid >> 3;
        float inv = 1.f / snorm[row];
        float4* dst = (float4*)(g_gn + ((size_t)bb * ROWSA + t0 + row) * Gn);
#pragma unroll
        for (int q = 0; q < 2; q++) {
            int f4 = (tid & 7) + q * 8;
            float4 v = *(const float4*)&xs[row][f4 * 4];
            v.x *= inv; v.y *= inv; v.z *= inv; v.w *= inv;
            dst[f4] = v;
        }
    }
}

// ---------------- K1b: round-1 adjacent sims ----------------
__global__ void k_sim()
{
    int b = blockIdx.y;
    int warp = threadIdx.x >> 5;
    int lane = threadIdx.x & 31;
    int i = (blockIdx.x * 8 + warp) * 2 + (lane >> 4);
    int l = lane & 15;
    float d = 0.f;
    if (i < Ln - 1) {
        const float4* A = (const float4*)(g_gn + ((size_t)b * ROWSA + i) * Gn);
        float4 a = A[l], c = A[l + 16];
        d = a.x * c.x + a.y * c.y + a.z * c.z + a.w * c.w;
    }
    d += __shfl_down_sync(0xffffffffu, d, 8, 16);
    d += __shfl_down_sync(0xffffffffu, d, 4, 16);
    d += __shfl_down_sync(0xffffffffu, d, 2, 16);
    d += __shfl_down_sync(0xffffffffu, d, 1, 16);
    if (l == 0 && i < Ln - 1) g_sim[b * Ln + i] = d;
}

// ---------------- K2a: per-round control (scalar only; CT=512) ----------------
__global__ __launch_bounds__(CT) void k_ctl(int rnd, int fin)
{
    const int b = blockIdx.x;
    const int tid = threadIdx.x;
    const int wid = tid >> 5;
    const int lane = tid & 31;

    int n = g_nn[b], rem = g_rm[b];
    if (rem <= 0 || n < 2) {
        if (tid == 0) { g_pc[b] = 0; g_ec[b] = 0; }
        return;
    }
    int r_step = min(rem, n >> 1);

    __shared__ float s_sim[Ln];
    __shared__ float s_norm[Ln];
    __shared__ unsigned short s_lo[Ln + 1];
    __shared__ int s_row[Ln];
    __shared__ unsigned char s_flag[Ln];
    __shared__ unsigned char s_isPair[Ln];
    __shared__ unsigned long long s_key[Ln];
    __shared__ int s_part[CT / 32];
    __shared__ int sh_pc, sh_ec;

    for (int i = tid; i < n; i += CT) {
        s_sim[i]  = g_sim[b * Ln + i];
        s_norm[i] = g_norms[b * Ln + i];
        s_lo[i]   = g_slo[b][i];
        s_row[i]  = g_srow[b][i];
    }
    if (tid == 0) { s_lo[n] = (unsigned short)Ln; sh_pc = 0; sh_ec = 0; }
    __syncthreads();

    int base = tid * CE;
    unsigned pre = 0, parF = 0, parB = 0;

    int run = -1;
#pragma unroll
    for (int e = 0; e < CE; e++) {
        int i = base + e;
        if (i < n - 1) {
            bool bnd = (i == 0) || (s_sim[i - 1] < s_sim[i]);
            if (bnd) run = i;
            if (run < 0) pre |= (1u << e);
            else if (((i - run) & 1) == 0) parF |= (1u << e);
        }
    }
    int incl = run;
#pragma unroll
    for (int off = 1; off < 32; off <<= 1) {
        int v = __shfl_up_sync(0xffffffffu, incl, off);
        if (lane >= off) incl = max(incl, v);
    }
    int excl = __shfl_up_sync(0xffffffffu, incl, 1);
    if (lane == 0) excl = -1;
    if (lane == 31) s_part[wid] = incl;
    __syncthreads();
    {
        int carry = excl;
        for (int w2 = 0; w2 < wid; w2++) carry = max(carry, s_part[w2]);
        if (pre) {
#pragma unroll
            for (int e = 0; e < CE; e++)
                if ((pre >> e) & 1u) {
                    if ((((base + e) - carry) & 1) == 0) parF |= (1u << e);
                }
        }
    }
    __syncthreads();

    pre = 0; run = 0x7fffffff;
#pragma unroll
    for (int e = CE - 1; e >= 0; e--) {
        int i = base + e;
        if (i < n - 1) {
            bool bnd = (i == n - 2) || (s_sim[i + 1] <= s_sim[i]);
            if (bnd) run = i;
            if (run == 0x7fffffff) pre |= (1u << e);
            else if (((run - i) & 1) == 0) parB |= (1u << e);
        }
    }
    int sincl = run;
#pragma unroll
    for (int off = 1; off < 32; off <<= 1) {
        int v = __shfl_down_sync(0xffffffffu, sincl, off);
        if (lane + off < 32) sincl = min(sincl, v);
    }
    int sexcl = __shfl_down_sync(0xffffffffu, sincl, 1);
    if (lane == 31) sexcl = 0x7fffffff;
    if (lane == 0) s_part[wid] = sincl;
    __syncthreads();
    {
        int carry = sexcl;
        for (int w2 = wid + 1; w2 < CT / 32; w2++) carry = min(carry, s_part[w2]);
        if (pre) {
#pragma unroll
            for (int e = 0; e < CE; e++)
                if ((pre >> e) & 1u) {
                    if (((carry - (base + e)) & 1) == 0) parB |= (1u << e);
                }
        }
    }

    unsigned tk = parF & parB;
    int lm = 0;
#pragma unroll
    for (int e = 0; e < CE; e++) {
        int i = base + e;
        if (i < n - 1) {
            unsigned t1 = (tk >> e) & 1u;
            s_flag[i] = (unsigned char)t1;
            lm += (int)t1;
        }
    }
#pragma unroll
    for (int off = 16; off > 0; off >>= 1) lm += __shfl_down_sync(0xffffffffu, lm, off);
    __syncthreads();
    if (lane == 0) s_part[wid] = lm;
    __syncthreads();
    int m = 0;
    for (int w2 = 0; w2 < CT / 32; w2++) m += s_part[w2];
    int cnt = min(m, r_step);

    if (m > r_step) {
        int P = 1; while (P < n - 1) P <<= 1;
        for (int i = tid; i < P; i += CT) {
            unsigned long long key = 0ull;
            if (i < n - 1 && (s_flag[i] & 1)) {
                unsigned u = __float_as_uint(s_sim[i]);
                unsigned sk = (u & 0x80000000u) ? ~u : (u | 0x80000000u);
                key = ((unsigned long long)sk << 16) | (unsigned)(Ln - 1 - i);
            }
            s_key[i] = key;
        }
        __syncthreads();
        for (int kk = 2; kk <= P; kk <<= 1) {
            for (int j = kk >> 1; j > 0; j >>= 1) {
                for (int i = tid; i < P; i += CT) {
                    int ixj = i ^ j;
                    if (ixj > i) {
                        unsigned long long a = s_key[i], c = s_key[ixj];
                        bool dir = ((i & kk) == 0);
                        if (dir ? (a < c) : (a > c)) { s_key[i] = c; s_key[ixj] = a; }
                    }
                }
                __syncthreads();
            }
        }
        for (int r = tid; r < r_step; r += CT) {
            int idx = Ln - 1 - (int)(s_key[r] & 0xFFFFull);
            s_flag[idx] |= 2;
        }
    } else {
        for (int i = tid; i < n - 1; i += CT)
            if (s_flag[i] & 1) s_flag[i] |= 2;
    }
    __syncthreads();

    int keepMask = 0, loc = 0;
#pragma unroll
    for (int e = 0; e < CE; e++) {
        int i = base + e;
        bool kp = (i < n) && !(i > 0 && (s_flag[i - 1] & 2));
        if (kp) { keepMask |= (1 << e); loc++; }
    }
    int inc = loc;
#pragma unroll
    for (int off = 1; off < 32; off <<= 1) {
        int v = __shfl_up_sync(0xffffffffu, inc, off);
        if (lane >= off) inc += v;
    }
    int exc = inc - loc;
    if (lane == 31) s_part[wid] = inc;
    __syncthreads();
    int carry = 0;
    for (int w2 = 0; w2 < wid; w2++) carry += s_part[w2];
    int p = carry + exc;
#pragma unroll
    for (int e = 0; e < CE; e++) {
        if ((keepMask >> e) & 1) {
            int i = base + e;
            bool isSel = (i < n - 1) && (s_flag[i] & 2);
            float wi2 = s_norm[i];
            g_norms[b * Ln + p] = isSel ? (wi2 + s_norm[i + 1]) * 0.5f : wi2;
            g_sim[b * Ln + p]   = s_sim[i];
            g_slo[b][p]         = s_lo[i];
            s_isPair[p] = isSel ? 1 : 0;
            g_iA[b][p]  = s_row[i];
            g_iB[b][p]  = isSel ? s_row[i + 1] : s_row[i];
            g_fw1[b][p] = wi2;
            g_fw2[b][p] = isSel ? s_norm[i + 1] : 0.f;
            g_isp[b][p] = isSel ? 1 : 0;
            if (fin && p < Tn) {
                if (isSel) {
                    float tot = wi2 + s_norm[i + 1] + EPSW;
                    g_lfa[b][p] = wi2 / tot;
                    g_lfb[b][p] = s_norm[i + 1] / tot;
                    g_ltb[b][p] = s_lo[i + 1];
                } else {
                    g_lfa[b][p] = 1.f;
                    g_lfb[b][p] = 1.f;
                    g_ltb[b][p] = 0;
                }
            }
            if (isSel) {
                int k = atomicAdd(&sh_pc, 1);
                int destRow = Ln + rnd * (Ln / 2) + k;
                g_srow[b][p] = destRow;
                PairRec pr;
                pr.p = p; pr.ta = s_lo[i]; pr.tb = s_lo[i + 1]; pr.tc = s_lo[i + 2];
                pr.wi = wi2; pr.wj = s_norm[i + 1];
                pr.rowA = s_row[i]; pr.rowB = s_row[i + 1]; pr.destRow = destRow;
                g_pairs[b][k] = pr;
            } else {
                g_srow[b][p] = s_row[i];
            }
            p++;
        }
    }
    __syncthreads();

    int n_new = n - cnt;
    int pc = sh_pc;
    if (!fin) {
        for (int k = tid; k < pc; k += CT) {
            int pp = g_pairs[b][k].p;
            if (pp + 1 < n_new) g_edges[b][atomicAdd(&sh_ec, 1)] = pp;
            if (pp > 0 && !s_isPair[pp - 1]) g_edges[b][atomicAdd(&sh_ec, 1)] = pp - 1;
        }
        __syncthreads();
    }

    if (tid == 0) {
        g_slo[b][n_new] = (unsigned short)Ln;
        g_nn[b] = n_new;
        g_rm[b] = rem - cnt;
        g_pc[b] = pc;
        g_ec[b] = sh_ec;
    }
}

// slot endpoint value from OLD rows (bit-matching the merge path)
__device__ __forceinline__ float4 slot_value(int b, int pos, int l, bool valid)
{
    int rowA = 0, rowB = 0, isp = 0;
    float w1 = 1.f, w2 = 0.f;
    if (valid) {
        rowA = g_iA[b][pos]; rowB = g_iB[b][pos];
        w1 = g_fw1[b][pos];  w2 = g_fw2[b][pos];
        isp = g_isp[b][pos];
    }
    float4 a = ((const float4*)(g_gn + ((size_t)b * ROWSA + rowA) * Gn))[l];
    float4 c = ((const float4*)(g_gn + ((size_t)b * ROWSA + rowB) * Gn))[l];
    float tot = w1 + w2 + EPSW;
    float mx = (w1 * a.x + w2 * c.x) / tot;
    float my = (w1 * a.y + w2 * c.y) / tot;
    float mz = (w1 * a.z + w2 * c.z) / tot;
    float mw = (w1 * a.w + w2 * c.w) / tot;
    float ssq = mx * mx + my * my + mz * mz + mw * mw;
    ssq += __shfl_xor_sync(0xffffffffu, ssq, 8, 16);
    ssq += __shfl_xor_sync(0xffffffffu, ssq, 4, 16);
    ssq += __shfl_xor_sync(0xffffffffu, ssq, 2, 16);
    ssq += __shfl_xor_sync(0xffffffffu, ssq, 1, 16);
    float inv = 1.f / fmaxf(sqrtf(ssq), EPSN);
    float4 v;
    v.x = isp ? mx * inv : a.x;
    v.y = isp ? my * inv : a.y;
    v.z = isp ? mz * inv : a.z;
    v.w = isp ? mw * inv : a.w;
    return v;
}

// ---------------- K2b: fused pair merges + edge sims ----------------
__global__ __launch_bounds__(256) void k_pair()
{
    int b = blockIdx.y;
    int l = threadIdx.x & 15;

    if (blockIdx.x < 64) {
        int hw = blockIdx.x * 16 + (threadIdx.x >> 4);
        int cnt = g_pc[b];
        bool valid = hw < cnt;

        int ta = 0, tb = 0, tc = 0, rowA = 0, rowB = 0, destRow = 0;
        float wi = 0.f, wj = 0.f, tot = 1.f;
        float4 a = make_float4(0.f, 0.f, 0.f, 0.f);
        float4 c = a;
        if (valid) {
            PairRec pr = g_pairs[b][hw];
            ta = pr.ta; tb = pr.tb; tc = pr.tc; wi = pr.wi; wj = pr.wj;
            rowA = pr.rowA; rowB = pr.rowB; destRow = pr.destRow;
            tot = wi + wj + EPSW;
            a = ((const float4*)(g_gn + ((size_t)b * ROWSA + rowA) * Gn))[l];
            c = ((const float4*)(g_gn + ((size_t)b * ROWSA + rowB) * Gn))[l];
        }
        float mx = (wi * a.x + wj * c.x) / tot;
        float my = (wi * a.y + wj * c.y) / tot;
        float mz = (wi * a.z + wj * c.z) / tot;
        float mw = (wi * a.w + wj * c.w) / tot;
        float ssq = mx * mx + my * my + mz * mz + mw * mw;
        ssq += __shfl_xor_sync(0xffffffffu, ssq, 8, 16);
        ssq += __shfl_xor_sync(0xffffffffu, ssq, 4, 16);
        ssq += __shfl_xor_sync(0xffffffffu, ssq, 2, 16);
        ssq += __shfl_xor_sync(0xffffffffu, ssq, 1, 16);
        if (valid) {
            float inv = 1.f / fmaxf(sqrtf(ssq), EPSN);
            float4 o; o.x = mx * inv; o.y = my * inv; o.z = mz * inv; o.w = mw * inv;
            ((float4*)(g_gn + ((size_t)b * ROWSA + destRow) * Gn))[l] = o;
            float fa = wi / tot, fb = wj / tot;
            float* cb = g_coef + b * Ln;
            for (int t = ta + l; t < tb; t += 16) cb[t] *= fa;
            for (int t = tb + l; t < tc; t += 16) cb[t] *= fb;
        }
    } else {
        int hw = (blockIdx.x - 64) * 16 + (threadIdx.x >> 4);
        int ec = g_ec[b];
        bool valid = hw < ec;
        int pos = valid ? g_edges[b][hw] : 0;

        float4 vu = slot_value(b, pos, l, valid);
        float4 vv = slot_value(b, pos + 1, l, valid);
        float d = vu.x * vv.x + vu.y * vv.y + vu.z * vv.z + vu.w * vv.w;
        d += __shfl_down_sync(0xffffffffu, d, 8, 16);
        d += __shfl_down_sync(0xffffffffu, d, 4, 16);
        d += __shfl_down_sync(0xffffffffu, d, 2, 16);
        d += __shfl_down_sync(0xffffffffu, d, 1, 16);
        if (valid && l == 0) g_sim[b * Ln + pos] = d;
    }
}

// ---------------- K3: apply plan (R14-measured-best; + final-round factors) ---
__global__ void k_apply(const float* __restrict__ x, const float* __restrict__ s,
                        float* __restrict__ out)
{
    int kslot = blockIdx.x;
    int chunk = blockIdx.y;
    int b = blockIdx.z;
    int lo = g_slo[b][kslot];
    int hi = g_slo[b][kslot + 1];
    int t4 = threadIdx.x;

    if (chunk == 0) {
        float lfa = g_lfa[b][kslot], lfb = g_lfb[b][kslot];
        int ltb = g_ltb[b][kslot];
        float4 acc = make_float4(0.f, 0.f, 0.f, 0.f);
#pragma unroll 2
        for (int t = lo; t < hi; t++) {
            float f = (t < ltb) ? lfa : lfb;
            float c = g_coef[b * Ln + t] * f;
            float4 v = ((const float4*)(x + ((size_t)b * Ln + t) * Dn))[t4];
            acc.x += c * v.x; acc.y += c * v.y; acc.z += c * v.z; acc.w += c * v.w;
        }
        ((float4*)(out + ((size_t)b * Tn + kslot) * Dn))[t4] = acc;
    } else {
        int c0 = (chunk - 1) * 512;
        float4 acc = make_float4(0.f, 0.f, 0.f, 0.f);
#pragma unroll 2
        for (int t = lo; t < hi; t++) {
            float4 v = ((const float4*)(s + ((size_t)b * Ln + t) * Nn + c0))[t4];
            acc.x += v.x; acc.y += v.y; acc.z += v.z; acc.w += v.w;
        }
        ((float4*)(out + (size_t)Bn * Tn * Dn + ((size_t)b * Tn + kslot) * Nn + c0))[t4] = acc;
    }
}

// ---------------- launch ----------------
extern "C" void kernel_launch(void* const* d_in, const int* in_sizes, int n_in,
                              void* d_out, int out_size)
{
    const float* x = (const float*)d_in[0];
    const float* src = (const float*)d_in[1];
    const float* w = (const float*)d_in[2];
    float* out = (float*)d_out;

    k_gn<<<Bn * Ln / 32, 256>>>(x, w);            // #0
    k_sim<<<dim3(128, Bn), 256>>>();              // #1
    for (int r = 0; r < RND; r++) {
        int fin = (r == RND - 1);
        k_ctl<<<Bn, CT>>>(r, fin);                // #2,4,6
        if (!fin) k_pair<<<dim3(192, Bn), 256>>>();  // #3,5
    }
    dim3 g3(Tn, 1 + Nn / 512, Bn);
    k_apply<<<g3, 128>>>(x, src, out);            // #7 — 8 launches total
}